// round 1
// baseline (speedup 1.0000x reference)
#include <cuda_runtime.h>
#include <cstdint>

// SoftTree: x[4096,512], gw[512,255], gb[255], pw[64,512,256], pb[64,256]
// out[4096,64] = einsum('bol,bl->bo', x@pw + pb, leaf_probs)
//
// Kernel 1: gatings + tree-path leaf probabilities -> d_leafp[4096,256]
// Kernel 2: fused GEMM (per head o: C[b,l] = x@pw[o]) + epilogue reduction
//           out[b,o] = sum_l p[b,l]*(C[b,l] + pb[o,l])

#define N_BATCH   4096
#define N_IN      512
#define N_OUT     64
#define N_LEAF    256
#define N_GATE    255
#define TREE_DEPTH 8

// Scratch for leaf probabilities (4 MB). Device globals are the allowed
// scratch mechanism (no cudaMalloc permitted).
__device__ float d_leafp[N_BATCH * N_LEAF];

// ---------------------------------------------------------------------------
// Packed fp32x2 helpers (Blackwell FFMA2 path — PTX-only per SASS docs)
// ---------------------------------------------------------------------------
__device__ __forceinline__ unsigned long long ffma2(unsigned long long a,
                                                    unsigned long long b,
                                                    unsigned long long c) {
    unsigned long long d;
    asm("fma.rn.f32x2 %0, %1, %2, %3;" : "=l"(d) : "l"(a), "l"(b), "l"(c));
    return d;
}
__device__ __forceinline__ unsigned long long pack2(float x) {
    unsigned long long d;
    unsigned int u = __float_as_uint(x);
    asm("mov.b64 %0, {%1, %1};" : "=l"(d) : "r"(u));
    return d;
}
__device__ __forceinline__ float2 unpack2(unsigned long long v) {
    float2 f;
    asm("mov.b64 {%0, %1}, %2;" : "=f"(f.x), "=f"(f.y) : "l"(v));
    return f;
}

// ---------------------------------------------------------------------------
// Kernel 1: gates + leaf probabilities.
// One block handles 8 batch rows. 256 threads.
//   Phase A: stage 8 x-rows in smem.
//   Phase B: thread t (<255) computes gate t for all 8 rows (gw loads coalesced,
//            x broadcast from smem), applies sigmoid.
//   Phase C: thread l walks the tree path of leaf l for each row.
// ---------------------------------------------------------------------------
#define K1_ROWS 8

__global__ __launch_bounds__(256) void softtree_gates_kernel(
    const float* __restrict__ x,
    const float* __restrict__ gw,
    const float* __restrict__ gb)
{
    __shared__ float xs[K1_ROWS][N_IN];    // 16 KB
    __shared__ float gs[K1_ROWS][N_LEAF];  // 8 KB (255 gates + pad)

    const int tid = threadIdx.x;
    const int b0  = blockIdx.x * K1_ROWS;

    // Phase A: rows b0..b0+7 are contiguous in global memory.
    {
        const float4* src = reinterpret_cast<const float4*>(x + (size_t)b0 * N_IN);
        float4* dst = reinterpret_cast<float4*>(&xs[0][0]);
        #pragma unroll
        for (int it = 0; it < (K1_ROWS * N_IN / 4) / 256; ++it) {
            int idx = it * 256 + tid;
            dst[idx] = src[idx];
        }
    }
    __syncthreads();

    // Phase B: gates
    if (tid < N_GATE) {
        float acc[K1_ROWS];
        const float bias = gb[tid];
        #pragma unroll
        for (int r = 0; r < K1_ROWS; ++r) acc[r] = bias;

        #pragma unroll 4
        for (int i = 0; i < N_IN; ++i) {
            float w = gw[i * N_GATE + tid];
            #pragma unroll
            for (int r = 0; r < K1_ROWS; ++r)
                acc[r] = fmaf(xs[r][i], w, acc[r]);
        }
        #pragma unroll
        for (int r = 0; r < K1_ROWS; ++r)
            gs[r][tid] = 1.0f / (1.0f + expf(-acc[r]));
    }
    __syncthreads();

    // Phase C: leaf probabilities. Matches reference tree_paths():
    // bits MSB-first, bit==1 -> (1-g), index = 2*index + bit, gate = index-1.
    const int l = tid;
    #pragma unroll
    for (int r = 0; r < K1_ROWS; ++r) {
        float p = 1.0f;
        int index = 1;
        #pragma unroll
        for (int j = 0; j < TREE_DEPTH; ++j) {
            int bit = (l >> (TREE_DEPTH - 1 - j)) & 1;
            float g = gs[r][index - 1];
            p *= bit ? (1.0f - g) : g;
            index = 2 * index + bit;
        }
        d_leafp[(size_t)(b0 + r) * N_LEAF + l] = p;
    }
}

// ---------------------------------------------------------------------------
// Kernel 2: fused per-head GEMM + leaf reduction.
// Grid: (batch_tiles=64, heads=64). Block: 256 threads.
// CTA computes C[64 x 256] = x_tile[64 x 512] @ pw[o][512 x 256] with K-chunks
// of 16, FFMA2 accumulators (each thread: 8 m x 8 n as 8x4 packed pairs),
// then reduces over l with p-weights via warp shuffles. No C ever hits memory.
// ---------------------------------------------------------------------------
#define BM 64
#define BK 16
#define AS_STRIDE 68   // 64 + 4 pad; 272B row keeps float4 alignment, cuts STS conflicts

__global__ __launch_bounds__(256, 2) void softtree_gemm_kernel(
    const float* __restrict__ x,
    const float* __restrict__ pw,
    const float* __restrict__ pb,
    float* __restrict__ out)
{
    __shared__ float As[BK][AS_STRIDE];  // A tile stored [k][m]
    __shared__ float Bs[BK][N_LEAF];     // B tile stored [k][l]

    const int tid = threadIdx.x;
    const int o   = blockIdx.y;
    const int b0  = blockIdx.x * BM;
    const int tm  = tid >> 5;   // 0..7 (warp id) -> m group of 8 rows
    const int tn  = tid & 31;   // lane -> n group of 8 leaves

    const float* __restrict__ pwo = pw + (size_t)o * N_IN * N_LEAF;

    unsigned long long acc[8][4];
    #pragma unroll
    for (int mi = 0; mi < 8; ++mi)
        #pragma unroll
        for (int ni = 0; ni < 4; ++ni) acc[mi][ni] = 0ull;  // {0.f, 0.f}

    for (int kt = 0; kt < N_IN / BK; ++kt) {
        // Load A tile (64 rows x 16 k), transpose to [k][m] in smem.
        {
            int m  = tid >> 2;          // 0..63
            int kq = (tid & 3) * 4;     // 0,4,8,12
            float4 v = *reinterpret_cast<const float4*>(
                x + (size_t)(b0 + m) * N_IN + kt * BK + kq);
            As[kq + 0][m] = v.x;
            As[kq + 1][m] = v.y;
            As[kq + 2][m] = v.z;
            As[kq + 3][m] = v.w;
        }
        // Load B tile (16 k x 256 l), l contiguous in pw -> coalesced float4.
        #pragma unroll
        for (int it = 0; it < 4; ++it) {
            int idx = it * 256 + tid;
            int k   = idx >> 6;          // 0..15
            int l4  = (idx & 63) * 4;    // 0..252
            *reinterpret_cast<float4*>(&Bs[k][l4]) =
                *reinterpret_cast<const float4*>(pwo + (size_t)(kt * BK + k) * N_LEAF + l4);
        }
        __syncthreads();

        #pragma unroll
        for (int kk = 0; kk < BK; ++kk) {
            // a: broadcast within warp (tm constant per warp)
            float4 a0 = *reinterpret_cast<const float4*>(&As[kk][tm * 8]);
            float4 a1 = *reinterpret_cast<const float4*>(&As[kk][tm * 8 + 4]);
            // b: 8 leaves as 4 packed pairs
            ulonglong2 bb0 = *reinterpret_cast<const ulonglong2*>(&Bs[kk][tn * 8]);
            ulonglong2 bb1 = *reinterpret_cast<const ulonglong2*>(&Bs[kk][tn * 8 + 4]);
            float a[8] = {a0.x, a0.y, a0.z, a0.w, a1.x, a1.y, a1.z, a1.w};
            #pragma unroll
            for (int mi = 0; mi < 8; ++mi) {
                unsigned long long pa = pack2(a[mi]);
                acc[mi][0] = ffma2(pa, bb0.x, acc[mi][0]);
                acc[mi][1] = ffma2(pa, bb0.y, acc[mi][1]);
                acc[mi][2] = ffma2(pa, bb1.x, acc[mi][2]);
                acc[mi][3] = ffma2(pa, bb1.y, acc[mi][3]);
            }
        }
        __syncthreads();
    }

    // Epilogue: s[mi] = sum over this thread's 8 leaves of p[b,l]*(C+pb[o,l]),
    // then warp-reduce across tn (each warp owns all 256 leaves for its 8 rows).
    float s[8];
    #pragma unroll
    for (int mi = 0; mi < 8; ++mi) s[mi] = 0.0f;

    #pragma unroll
    for (int ni = 0; ni < 4; ++ni) {
        int n = tn * 8 + ni * 2;
        float pb0 = pb[o * N_LEAF + n];
        float pb1 = pb[o * N_LEAF + n + 1];
        #pragma unroll
        for (int mi = 0; mi < 8; ++mi) {
            int b = b0 + tm * 8 + mi;
            float2 c = unpack2(acc[mi][ni]);
            float p0 = d_leafp[(size_t)b * N_LEAF + n];
            float p1 = d_leafp[(size_t)b * N_LEAF + n + 1];
            s[mi] = fmaf(c.x + pb0, p0, s[mi]);
            s[mi] = fmaf(c.y + pb1, p1, s[mi]);
        }
    }

    #pragma unroll
    for (int mi = 0; mi < 8; ++mi) {
        float v = s[mi];
        #pragma unroll
        for (int off = 16; off > 0; off >>= 1)
            v += __shfl_xor_sync(0xffffffffu, v, off);
        if (tn == 0)
            out[(size_t)(b0 + tm * 8 + mi) * N_OUT + o] = v;
    }
}

// ---------------------------------------------------------------------------
extern "C" void kernel_launch(void* const* d_in, const int* in_sizes, int n_in,
                              void* d_out, int out_size)
{
    const float* x  = (const float*)d_in[0];
    const float* gw = (const float*)d_in[1];
    const float* gb = (const float*)d_in[2];
    const float* pw = (const float*)d_in[3];
    const float* pb = (const float*)d_in[4];
    // d_in[5] (leaf_idx) / d_in[6] (leaf_bit) unused: paths are recomputed
    // arithmetically, identical to the reference construction.
    float* out = (float*)d_out;

    softtree_gates_kernel<<<N_BATCH / K1_ROWS, 256>>>(x, gw, gb);

    dim3 grid(N_BATCH / BM, N_OUT);
    softtree_gemm_kernel<<<grid, 256>>>(x, pw, pb, out);
}

// round 5
// speedup vs baseline: 2.9214x; 2.9214x over previous
#include <cuda_runtime.h>
#include <cstdint>

// SoftTree: x[4096,512], gw[512,255], gb[255], pw[64,512,256], pb[64,256]
// out[b,o] = sum_l leafp[b,l] * ((x @ pw[o])[b,l] + pb[o,l])
//
// R5: build target is plain sm_100 (tcgen05 rejected by ptxas) -> use
// mma.sync.aligned.m16n8k8 tf32 (sm_80+ path, legal on sm_100).
//
//   K0: xt  = rna_tf32(x)             (8 MB scratch)
//   K1: pwc = rna_tf32(pw)            (33.5 MB scratch, SAME layout [o][k][n])
//   K2: gates -> d_leafp[4096,256]
//   K3: tf32 mma.sync GEMM, CTA tile 128x256xK512, fused leafp epilogue.

#define N_BATCH   4096
#define N_IN      512
#define N_OUT     64
#define N_LEAF    256
#define N_GATE    255
#define TREE_DEPTH 8

__device__ float d_leafp[N_BATCH * N_LEAF];                    // 4 MB
__device__ float d_pwc[(size_t)N_OUT * N_IN * N_LEAF];         // 33.5 MB
__device__ float d_xt[N_BATCH * N_IN];                         // 8 MB

__device__ __forceinline__ float rna_tf32(float f) {
    uint32_t u;
    asm("cvt.rna.tf32.f32 %0, %1;" : "=r"(u) : "f"(f));
    return __uint_as_float(u);
}

__device__ __forceinline__ uint32_t smem_u32(const void* p) {
    uint32_t a;
    asm("{ .reg .u64 t; cvta.to.shared.u64 t, %1; cvt.u32.u64 %0, t; }"
        : "=r"(a) : "l"(p));
    return a;
}

#define CP_ASYNC16(dst_u32, src_ptr) \
    asm volatile("cp.async.cg.shared.global [%0], [%1], 16;" \
                 :: "r"(dst_u32), "l"(src_ptr))
#define CP_COMMIT()  asm volatile("cp.async.commit_group;" ::: "memory")
#define CP_WAIT1()   asm volatile("cp.async.wait_group 1;" ::: "memory")

__device__ __forceinline__ void mma_tf32(float* d, const uint32_t* a,
                                         const uint32_t* b) {
    asm volatile(
        "mma.sync.aligned.m16n8k8.row.col.f32.tf32.tf32.f32 "
        "{%0,%1,%2,%3}, {%4,%5,%6,%7}, {%8,%9}, {%0,%1,%2,%3};"
        : "+f"(d[0]), "+f"(d[1]), "+f"(d[2]), "+f"(d[3])
        : "r"(a[0]), "r"(a[1]), "r"(a[2]), "r"(a[3]), "r"(b[0]), "r"(b[1]));
}

// ---------------------------------------------------------------------------
// K0: rna-round x
// ---------------------------------------------------------------------------
__global__ __launch_bounds__(256) void xt_kernel(const float* __restrict__ x) {
    int i = blockIdx.x * 256 + threadIdx.x;
    float4 v = reinterpret_cast<const float4*>(x)[i];
    v.x = rna_tf32(v.x); v.y = rna_tf32(v.y);
    v.z = rna_tf32(v.z); v.w = rna_tf32(v.w);
    reinterpret_cast<float4*>(d_xt)[i] = v;
}
// K1: rna-round pw (layout preserved)
__global__ __launch_bounds__(256) void pwc_kernel(const float* __restrict__ pw) {
    int i = blockIdx.x * 256 + threadIdx.x;
    float4 v = reinterpret_cast<const float4*>(pw)[i];
    v.x = rna_tf32(v.x); v.y = rna_tf32(v.y);
    v.z = rna_tf32(v.z); v.w = rna_tf32(v.w);
    reinterpret_cast<float4*>(d_pwc)[i] = v;
}

// ---------------------------------------------------------------------------
// K2: gates + leaf probabilities (proven in R1)
// ---------------------------------------------------------------------------
#define K1_ROWS 8
__global__ __launch_bounds__(256) void softtree_gates_kernel(
    const float* __restrict__ x, const float* __restrict__ gw,
    const float* __restrict__ gb)
{
    __shared__ float xs[K1_ROWS][N_IN];
    __shared__ float gs[K1_ROWS][N_LEAF];
    const int tid = threadIdx.x;
    const int b0  = blockIdx.x * K1_ROWS;

    {
        const float4* src = reinterpret_cast<const float4*>(x + (size_t)b0 * N_IN);
        float4* dst = reinterpret_cast<float4*>(&xs[0][0]);
        #pragma unroll
        for (int it = 0; it < (K1_ROWS * N_IN / 4) / 256; ++it)
            dst[it * 256 + tid] = src[it * 256 + tid];
    }
    __syncthreads();

    if (tid < N_GATE) {
        float acc[K1_ROWS];
        const float bias = gb[tid];
        #pragma unroll
        for (int r = 0; r < K1_ROWS; ++r) acc[r] = bias;
        #pragma unroll 4
        for (int i = 0; i < N_IN; ++i) {
            float w = gw[i * N_GATE + tid];
            #pragma unroll
            for (int r = 0; r < K1_ROWS; ++r)
                acc[r] = fmaf(xs[r][i], w, acc[r]);
        }
        #pragma unroll
        for (int r = 0; r < K1_ROWS; ++r)
            gs[r][tid] = 1.0f / (1.0f + expf(-acc[r]));
    }
    __syncthreads();

    const int l = tid;
    #pragma unroll
    for (int r = 0; r < K1_ROWS; ++r) {
        float p = 1.0f;
        int index = 1;
        #pragma unroll
        for (int j = 0; j < TREE_DEPTH; ++j) {
            int bit = (l >> (TREE_DEPTH - 1 - j)) & 1;
            float g = gs[r][index - 1];
            p *= bit ? (1.0f - g) : g;
            index = 2 * index + bit;
        }
        d_leafp[(size_t)(b0 + r) * N_LEAF + l] = p;
    }
}

// ---------------------------------------------------------------------------
// K3: tf32 mma.sync GEMM + fused epilogue.
// Grid (32 batch-tiles, 64 heads) = 2048 CTAs, 256 threads (8 warps, 2m x 4n).
// CTA tile M=128, N=256, BK=32 (4 k-steps of 8), cp.async double-buffered.
// Warp tile 64x64: 4 m-frags x 8 n-frags, acc[4][8][4].
// ---------------------------------------------------------------------------
#define BM 128
#define BN 256
#define BK 32
#define A_STRIDE 36     // floats; 144B rows (16B aligned), conflict-free frags
#define B_STRIDE 260    // floats; 1040B rows (16B aligned), conflict-free frags
#define A_STAGE (BM * A_STRIDE)          // floats
#define B_STAGE (BK * B_STRIDE)
#define SMEM_FLOATS (2 * A_STAGE + 2 * B_STAGE + 4 * BM)
#define N_STAGE 16      // K / BK

__global__ __launch_bounds__(256, 1) void softtree_gemm_mma(
    const float* __restrict__ pb, float* __restrict__ out)
{
    extern __shared__ float sm[];
    float* As  = sm;                          // 2 stages
    float* Bs  = sm + 2 * A_STAGE;            // 2 stages
    float* red = sm + 2 * A_STAGE + 2 * B_STAGE;  // [4][BM]

    const int tid  = threadIdx.x;
    const int lane = tid & 31;
    const int wid  = tid >> 5;
    const int wm   = wid >> 2;          // 0..1
    const int wn   = wid & 3;           // 0..3
    const int lq   = lane >> 2;         // 0..7
    const int lr   = lane & 3;          // 0..3
    const int o    = blockIdx.y;
    const int b0   = blockIdx.x * BM;

    const float* __restrict__ pwo = d_pwc + (size_t)o * N_IN * N_LEAF;

    // cp.async loader indices (per thread):
    // A: 4 x 16B; idx = it*256+tid; m = idx/8, kq = idx%8
    // B: 8 x 16B; idx = it*256+tid; k = idx/64, nq = idx%64
    auto load_stage = [&](int kt) {
        const int s = kt & 1;
        const int k0 = kt * BK;
        uint32_t a_base = smem_u32(As + s * A_STAGE);
        uint32_t b_base = smem_u32(Bs + s * B_STAGE);
        #pragma unroll
        for (int it = 0; it < 4; ++it) {
            int idx = it * 256 + tid;
            int m = idx >> 3, kq = idx & 7;
            CP_ASYNC16(a_base + (uint32_t)(m * A_STRIDE + 4 * kq) * 4,
                       d_xt + (size_t)(b0 + m) * N_IN + k0 + 4 * kq);
        }
        #pragma unroll
        for (int it = 0; it < 8; ++it) {
            int idx = it * 256 + tid;
            int k = idx >> 6, nq = idx & 63;
            CP_ASYNC16(b_base + (uint32_t)(k * B_STRIDE + 4 * nq) * 4,
                       pwo + (size_t)(k0 + k) * N_LEAF + 4 * nq);
        }
        CP_COMMIT();
    };

    float acc[4][8][4];
    #pragma unroll
    for (int mf = 0; mf < 4; ++mf)
        #pragma unroll
        for (int nf = 0; nf < 8; ++nf)
            #pragma unroll
            for (int e = 0; e < 4; ++e) acc[mf][nf][e] = 0.0f;

    load_stage(0);
    load_stage(1);

    for (int kt = 0; kt < N_STAGE; ++kt) {
        CP_WAIT1();
        __syncthreads();

        const int s = kt & 1;
        const float* Ab = As + s * A_STAGE + (wm * 64) * A_STRIDE;
        const float* Bb = Bs + s * B_STAGE;

        #pragma unroll
        for (int ks = 0; ks < 4; ++ks) {
            const int kk = ks * 8;
            uint32_t af[4][4], bf[8][2];
            #pragma unroll
            for (int mf = 0; mf < 4; ++mf) {
                const float* ap = Ab + (mf * 16 + lq) * A_STRIDE + kk + lr;
                af[mf][0] = __float_as_uint(ap[0]);
                af[mf][1] = __float_as_uint(ap[8 * A_STRIDE]);
                af[mf][2] = __float_as_uint(ap[4]);
                af[mf][3] = __float_as_uint(ap[8 * A_STRIDE + 4]);
            }
            #pragma unroll
            for (int nf = 0; nf < 8; ++nf) {
                const float* bp = Bb + (kk + lr) * B_STRIDE + wn * 64 + nf * 8 + lq;
                bf[nf][0] = __float_as_uint(bp[0]);
                bf[nf][1] = __float_as_uint(bp[4 * B_STRIDE]);
            }
            #pragma unroll
            for (int mf = 0; mf < 4; ++mf)
                #pragma unroll
                for (int nf = 0; nf < 8; ++nf)
                    mma_tf32(acc[mf][nf], af[mf], bf[nf]);
        }

        __syncthreads();
        if (kt + 2 < N_STAGE) load_stage(kt + 2);
    }

    // -----------------------------------------------------------------
    // Fused epilogue: s[row] = sum_n p[b,n]*(C[b,n] + pb[o,n])
    // c0,c1 -> row = wm*64+mf*16+lq,   cols n, n+1 (n = wn*64+nf*8+2*lr)
    // c2,c3 -> row+8
    // -----------------------------------------------------------------
    const float* __restrict__ pbo = pb + (size_t)o * N_LEAF;
    #pragma unroll
    for (int mf = 0; mf < 4; ++mf) {
        const int r0 = wm * 64 + mf * 16 + lq;
        const int r1 = r0 + 8;
        const float* p0row = d_leafp + (size_t)(b0 + r0) * N_LEAF;
        const float* p1row = d_leafp + (size_t)(b0 + r1) * N_LEAF;
        float s0 = 0.0f, s1 = 0.0f;
        #pragma unroll
        for (int nf = 0; nf < 8; ++nf) {
            const int n = wn * 64 + nf * 8 + 2 * lr;
            float2 pbv = *reinterpret_cast<const float2*>(pbo + n);
            float2 pa  = *reinterpret_cast<const float2*>(p0row + n);
            float2 pc  = *reinterpret_cast<const float2*>(p1row + n);
            s0 = fmaf(acc[mf][nf][0] + pbv.x, pa.x, s0);
            s0 = fmaf(acc[mf][nf][1] + pbv.y, pa.y, s0);
            s1 = fmaf(acc[mf][nf][2] + pbv.x, pc.x, s1);
            s1 = fmaf(acc[mf][nf][3] + pbv.y, pc.y, s1);
        }
        // reduce over lr (lanes sharing lq)
        s0 += __shfl_xor_sync(0xffffffffu, s0, 1);
        s0 += __shfl_xor_sync(0xffffffffu, s0, 2);
        s1 += __shfl_xor_sync(0xffffffffu, s1, 1);
        s1 += __shfl_xor_sync(0xffffffffu, s1, 2);
        if (lr == 0) {
            red[wn * BM + r0] = s0;
            red[wn * BM + r1] = s1;
        }
    }
    __syncthreads();

    if (tid < BM) {
        float v = red[0 * BM + tid] + red[1 * BM + tid] +
                  red[2 * BM + tid] + red[3 * BM + tid];
        out[(size_t)(b0 + tid) * N_OUT + o] = v;
    }
}

// ---------------------------------------------------------------------------
extern "C" void kernel_launch(void* const* d_in, const int* in_sizes, int n_in,
                              void* d_out, int out_size)
{
    const float* x  = (const float*)d_in[0];
    const float* gw = (const float*)d_in[1];
    const float* gb = (const float*)d_in[2];
    const float* pw = (const float*)d_in[3];
    const float* pb = (const float*)d_in[4];
    float* out = (float*)d_out;

    const int smem_bytes = SMEM_FLOATS * 4;
    cudaFuncSetAttribute(softtree_gemm_mma,
                         cudaFuncAttributeMaxDynamicSharedMemorySize, smem_bytes);

    xt_kernel<<<(N_BATCH * N_IN / 4) / 256, 256>>>(x);
    pwc_kernel<<<((size_t)N_OUT * N_IN * N_LEAF / 4) / 256, 256>>>(pw);
    softtree_gates_kernel<<<N_BATCH / K1_ROWS, 256>>>(x, gw, gb);

    dim3 grid(N_BATCH / BM, N_OUT);
    softtree_gemm_mma<<<grid, 256, smem_bytes>>>(pb, out);
}